// round 2
// baseline (speedup 1.0000x reference)
#include <cuda_runtime.h>

#define HH 128
#define WW 128
#define NIMG 2
#define NC 21
#define PL (HH * WW)

// scratch (no allocations allowed)
__device__ float    g_rgb[NIMG * 3 * PL];   // pooled rgb, pre-scaled by 10
__device__ float    g_txy[121];             // exp(-(dx^2+dy^2)/72)
__device__ double   g_acc;
__device__ unsigned g_cnt;

// ---------------------------------------------------------------------------
// Pass 1: vectorized 2x2 mean-pool (+ *10 scale), txy table, zero accumulators.
// One thread produces TWO pooled outputs from two float4 loads.
// ---------------------------------------------------------------------------
__global__ void prep_kernel(const float4* __restrict__ rgb) {
    int idx = blockIdx.x * blockDim.x + threadIdx.x;
    if (blockIdx.x == 0) {
        if (threadIdx.x == 0) { g_acc = 0.0; g_cnt = 0u; }
        if (threadIdx.x < 121) {
            int dy = (int)threadIdx.x / 11 - 5;
            int dx = (int)threadIdx.x % 11 - 5;
            g_txy[threadIdx.x] = __expf(-(float)(dx * dx + dy * dy) / 72.0f);
        }
    }
    const int total = NIMG * 3 * PL / 2;  // output pairs
    if (idx < total) {
        int xp = idx % (WW / 2);
        int y  = (idx / (WW / 2)) % HH;
        int nc = idx / ((WW / 2) * HH);
        // raw plane is 256x256; rows 2y,2y+1, cols 4xp..4xp+3
        const float4* p = rgb + (size_t)nc * (256 * 256 / 4) + (2 * y) * 64 + xp;
        float4 a = __ldg(p);
        float4 b = __ldg(p + 64);
        float2 o;
        o.x = (a.x + a.y + b.x + b.y) * 2.5f;  // 0.25 mean * 10 scale
        o.y = (a.z + a.w + b.z + b.w) * 2.5f;
        ((float2*)g_rgb)[idx] = o;
    }
}

// ---------------------------------------------------------------------------
// Pass 2: main CRF kernel with fused finalize.
// One warp per block, tile 32x2, V=2 vertical pixels per thread.
// A neighbor load at row offset r serves P0's tap (dy=r) and P1's tap (dy=r-1).
// Symmetric forward-tap halving: each in-bounds pair counted twice.
// OOB (zero-padded) taps contribute in closed form.
// ---------------------------------------------------------------------------
__global__ void __launch_bounds__(32) crf_kernel(const float* __restrict__ Y,
                                                 float* __restrict__ out,
                                                 int nblocks) {
    const int x  = blockIdx.x * 32 + threadIdx.x;
    const int y0 = blockIdx.y * 2;
    const int n  = blockIdx.z;

    const float* yb = Y + (size_t)n * NC * PL + y0 * WW + x;
    const float* gb = g_rgb + (size_t)n * 3 * PL + y0 * WW + x;

    float yc0[NC], yc1[NC];
#pragma unroll
    for (int c = 0; c < NC; c++) {
        yc0[c] = __ldg(yb + c * PL);
        yc1[c] = __ldg(yb + c * PL + WW);
    }
    const float r00 = __ldg(gb),      g00 = __ldg(gb + PL),      b00 = __ldg(gb + 2 * PL);
    const float r01 = __ldg(gb + WW), g01 = __ldg(gb + PL + WW), b01 = __ldg(gb + 2 * PL + WW);

    float term1 = 0.0f, term2 = 0.0f;

    // ---- OOB closed form for both pixels ----
    {
        int xl = max(x - 5, 0), xr = min(x + 5, WW - 1);
        float cw = (float)(xr - xl + 1);
        {
            int yl = max(y0 - 5, 0), yr = min(y0 + 5, HH - 1);
            float oob = 121.0f - cw * (float)(yr - yl + 1);
            float ep  = __expf(-(float)(x * x + y0 * y0) / 72.0f);
            float ec  = __expf(-0.5f * (r00 * r00 + g00 * g00 + b00 * b00));
            term1 += oob * ep * (0.9f * ec + 0.1f);
        }
        {
            int y1 = y0 + 1;
            int yl = max(y1 - 5, 0), yr = min(y1 + 5, HH - 1);
            float oob = 121.0f - cw * (float)(yr - yl + 1);
            float ep  = __expf(-(float)(x * x + y1 * y1) / 72.0f);
            float ec  = __expf(-0.5f * (r01 * r01 + g01 * g01 + b01 * b01));
            term1 += oob * ep * (0.9f * ec + 0.1f);
        }
    }

    // ---- shared-load tap processor (u0/u1 are compile-time after unroll) ----
    auto proc = [&](int r, int dx, bool u0, bool u1) {
        int nx = x + dx;
        if ((unsigned)nx < (unsigned)WW && (y0 + r) < HH) {
            int off = r * WW + dx;
            float vr = __ldg(gb + off);
            float vg = __ldg(gb + PL + off);
            float vb = __ldg(gb + 2 * PL + off);
            float d0a = 0.f, d0b = 0.f, d1a = 0.f, d1b = 0.f;
#pragma unroll
            for (int c = 0; c < NC; c += 2) {
                float v = __ldg(yb + c * PL + off);
                if (u0) d0a = fmaf(yc0[c], v, d0a);
                if (u1) d1a = fmaf(yc1[c], v, d1a);
                if (c + 1 < NC) {
                    float w = __ldg(yb + (c + 1) * PL + off);
                    if (u0) d0b = fmaf(yc0[c + 1], w, d0b);
                    if (u1) d1b = fmaf(yc1[c + 1], w, d1b);
                }
            }
            if (u0) {
                float dr = vr - r00, dg = vg - g00, db = vb - b00;
                float e = __expf(-0.5f * (dr * dr + dg * dg + db * db));
                float k = __ldg(&g_txy[(r + 5) * 11 + dx + 5]) * (0.9f * e + 0.1f);
                term1 += 2.0f * k;
                term2  = fmaf(2.0f * k, d0a + d0b, term2);
            }
            if (u1) {
                float dr = vr - r01, dg = vg - g01, db = vb - b01;
                float e = __expf(-0.5f * (dr * dr + dg * dg + db * db));
                float k = __ldg(&g_txy[(r + 4) * 11 + dx + 5]) * (0.9f * e + 0.1f);
                term1 += 2.0f * k;
                term2  = fmaf(2.0f * k, d1a + d1b, term2);
            }
        }
    };

    // r = 0: P0 taps (0, 1..5)
#pragma unroll
    for (int dx = 1; dx <= 5; dx++) proc(0, dx, true, false);
    // r = 1, dx <= 0: P0 tap (1, dx) only
#pragma unroll
    for (int dx = -5; dx <= 0; dx++) proc(1, dx, true, false);
    // r = 1, dx >= 1: P0 tap (1, dx) + P1 tap (0, dx)
#pragma unroll
    for (int dx = 1; dx <= 5; dx++) proc(1, dx, true, true);
    // r = 2..5: both pixels, all dx
#pragma unroll
    for (int r = 2; r <= 5; r++)
#pragma unroll
        for (int dx = -5; dx <= 5; dx++) proc(r, dx, true, true);
    // r = 6: P1 tap (5, dx) only
#pragma unroll
    for (int dx = -5; dx <= 5; dx++) proc(6, dx, false, true);

    // ---- warp reduce + fused finalize ----
    float v = term1 - term2;
#pragma unroll
    for (int s = 16; s > 0; s >>= 1)
        v += __shfl_down_sync(0xFFFFFFFFu, v, s);

    if (threadIdx.x == 0) {
        atomicAdd(&g_acc, (double)v);
        __threadfence();
        unsigned old = atomicAdd(&g_cnt, 1u);
        if (old == (unsigned)(nblocks - 1)) {
            double s = atomicAdd(&g_acc, 0.0);
            out[0] = (float)(s / (double)(NIMG * HH * WW));
            g_acc = 0.0;   // self-reset for next graph replay
            g_cnt = 0u;
        }
    }
}

extern "C" void kernel_launch(void* const* d_in, const int* in_sizes, int n_in,
                              void* d_out, int out_size) {
    const float* y   = (const float*)d_in[0];
    const float* rgb = (const float*)d_in[1];
    if (n_in >= 2 && in_sizes[0] == NIMG * 3 * 256 * 256) {
        const float* t = y; y = rgb; rgb = t;
    }

    const int pairs = NIMG * 3 * PL / 2;
    prep_kernel<<<(pairs + 255) / 256, 256>>>((const float4*)rgb);

    dim3 grid(WW / 32, HH / 2, NIMG);
    crf_kernel<<<grid, 32>>>(y, (float*)d_out, grid.x * grid.y * grid.z);
}

// round 3
// speedup vs baseline: 1.6250x; 1.6250x over previous
#include <cuda_runtime.h>
#include <cuda_bf16.h>

#define HH 128
#define WW 128
#define NIMG 2
#define NC 21
#define PL (HH * WW)
#define NPIX (NIMG * PL)
#define NSLOT 66          // 6 rows x 11 dx slots (some unused -> stay 0)
#define NBLK_B (64 * 3 * 2)

// scratch (static __device__ arrays are zero-initialized at module load;
// OOB K2 slots are never written and therefore stay exactly 0 forever)
__device__ float          g_rgb[NIMG * 3 * PL];   // pooled rgb, pre-scaled by 10
__device__ __nv_bfloat16  g_K2[NSLOT * NPIX];     // 2*kern per forward tap, bf16
__device__ double         g_acc;
__device__ unsigned       g_cnt;

// ---------------------------------------------------------------------------
// prep: 2x2 mean pool (+ *10 scale) of rgb, reset accumulators
// ---------------------------------------------------------------------------
__global__ void prep_kernel(const float4* __restrict__ rgb) {
    int idx = blockIdx.x * blockDim.x + threadIdx.x;
    if (idx == 0) { g_acc = 0.0; g_cnt = 0u; }
    const int total = NIMG * 3 * PL / 2;
    if (idx < total) {
        int xp = idx % (WW / 2);
        int y  = (idx / (WW / 2)) % HH;
        int nc = idx / ((WW / 2) * HH);
        const float4* p = rgb + (size_t)nc * (256 * 256 / 4) + (2 * y) * 64 + xp;
        float4 a = __ldg(p);
        float4 b = __ldg(p + 64);
        float2 o;
        o.x = (a.x + a.y + b.x + b.y) * 2.5f;
        o.y = (a.z + a.w + b.z + b.w) * 2.5f;
        ((float2*)g_rgb)[idx] = o;
    }
}

// ---------------------------------------------------------------------------
// Phase A: compute K2 field (2*kern, bf16) for the 60 forward taps.
// grid = (NIMG*HH rows, 4 tap-groups), block = 128 (one lane per x).
// Also accumulates term1 = sum(kernels) incl. OOB closed form (group 0).
// ---------------------------------------------------------------------------
__global__ __launch_bounds__(128) void phaseA_kernel() {
    const int x   = threadIdx.x;
    const int row = blockIdx.x;           // 0..255
    const int n   = row / HH;
    const int y   = row % HH;
    const int k   = blockIdx.y;           // 0..3

    const float* gb  = g_rgb + (size_t)n * 3 * PL + y * WW + x;
    const int    pix = n * PL + y * WW + x;

    const float r0 = __ldg(gb), g0 = __ldg(gb + PL), b0 = __ldg(gb + 2 * PL);
    float t1 = 0.0f;

#pragma unroll
    for (int i = 0; i < 15; i++) {
        int ti = k * 15 + i;               // global forward-tap index 0..59
        int r, dx;
        if (ti < 5) { r = 0; dx = ti + 1; }
        else        { int u = ti - 5; r = u / 11 + 1; dx = u % 11 - 5; }

        bool ok = (y + r < HH) && ((unsigned)(x + dx) < (unsigned)WW);
        if (ok) {
            int off = r * WW + dx;
            float dr = __ldg(gb + off) - r0;
            float dg = __ldg(gb + PL + off) - g0;
            float db = __ldg(gb + 2 * PL + off) - b0;
            float e   = __expf(-0.5f * (dr * dr + dg * dg + db * db));
            float exy = __expf((float)(dx * dx + r * r) * (-1.0f / 72.0f));
            float k2  = exy * (1.8f * e + 0.2f);   // 2 * txy * (0.9 e + 0.1)
            t1 += k2;
            g_K2[(r * 11 + dx + 5) * NPIX + pix] = __float2bfloat16(k2);
        }
    }

    if (k == 0) {  // OOB (zero-padded feature) taps in closed form, full 121-window
        int xl = max(x - 5, 0), xr = min(x + 5, WW - 1);
        int yl = max(y - 5, 0), yr = min(y + 5, HH - 1);
        float oob = 121.0f - (float)((xr - xl + 1) * (yr - yl + 1));
        float ep  = __expf((float)(x * x + y * y) * (-1.0f / 72.0f));
        float ec  = __expf(-0.5f * (r0 * r0 + g0 * g0 + b0 * b0));
        t1 += oob * ep * (0.9f * ec + 0.1f);
    }

    // block reduce + atomic
#pragma unroll
    for (int s = 16; s > 0; s >>= 1) t1 += __shfl_down_sync(0xFFFFFFFFu, t1, s);
    __shared__ float ws[4];
    int lane = threadIdx.x & 31, warp = threadIdx.x >> 5;
    if (lane == 0) ws[warp] = t1;
    __syncthreads();
    if (threadIdx.x == 0)
        atomicAdd(&g_acc, (double)(ws[0] + ws[1] + ws[2] + ws[3]));
}

// ---------------------------------------------------------------------------
// Phase B: term2. Thread = (4-pixel quad, 7-channel group, 3-row tap group).
// s[dx][px] = sum_c y_p * y_q accumulated from float4 row windows,
// then one K2 (bf16) pass. OOB taps contribute 0 because K2 slot == 0.
// grid = (64 quad-chunks, 3 cgroups, 2 rgroups), block = 128.
// ---------------------------------------------------------------------------
__global__ __launch_bounds__(128) void phaseB_kernel(const float* __restrict__ Y,
                                                     float* __restrict__ out) {
    const int quad = blockIdx.x * 128 + threadIdx.x;   // 0..8191
    const int n  = quad >> 12;
    const int y  = (quad >> 5) & (HH - 1);
    const int x0 = (quad & 31) << 2;
    const int cg = blockIdx.y;   // 0..2
    const int rg = blockIdx.z;   // 0..1

    const float* ybase = Y + (size_t)n * NC * PL + (size_t)cg * 7 * PL;

    const bool pm2 = (x0 >= 8), pm1 = (x0 >= 4);
    const bool pp1 = (x0 <= 120), pp2 = (x0 <= 116);
    const float4 Z4 = {0.f, 0.f, 0.f, 0.f};

    // center values for the quad, 7 channels
    float yp[7][4];
#pragma unroll
    for (int c = 0; c < 7; c++) {
        float4 v = __ldg((const float4*)(ybase + (size_t)c * PL + y * WW + x0));
        yp[c][0] = v.x; yp[c][1] = v.y; yp[c][2] = v.z; yp[c][3] = v.w;
    }

    float t2a[4] = {0.f, 0.f, 0.f, 0.f};

#pragma unroll
    for (int rr = 0; rr < 3; rr++) {
        int r = rg * 3 + rr;
        if (y + r < HH) {
            float s[11][4];
#pragma unroll
            for (int d = 0; d < 11; d++)
#pragma unroll
                for (int p = 0; p < 4; p++) s[d][p] = 0.f;

#pragma unroll
            for (int c = 0; c < 7; c++) {
                const float* rb = ybase + (size_t)c * PL + (y + r) * WW + x0;
                float w[20];
                float4 v;
                v = pm2 ? __ldg((const float4*)(rb - 8)) : Z4;
                w[0] = v.x; w[1] = v.y; w[2] = v.z; w[3] = v.w;
                v = pm1 ? __ldg((const float4*)(rb - 4)) : Z4;
                w[4] = v.x; w[5] = v.y; w[6] = v.z; w[7] = v.w;
                v = __ldg((const float4*)(rb));
                w[8] = v.x; w[9] = v.y; w[10] = v.z; w[11] = v.w;
                v = pp1 ? __ldg((const float4*)(rb + 4)) : Z4;
                w[12] = v.x; w[13] = v.y; w[14] = v.z; w[15] = v.w;
                v = pp2 ? __ldg((const float4*)(rb + 8)) : Z4;
                w[16] = v.x; w[17] = v.y; w[18] = v.z; w[19] = v.w;

#pragma unroll
                for (int d = 0; d < 11; d++)
#pragma unroll
                    for (int p = 0; p < 4; p++)
                        s[d][p] = fmaf(yp[c][p], w[3 + p + d], s[d][p]);
            }

            const __nv_bfloat16* kb = g_K2 + (size_t)(r * 11) * NPIX
                                    + (n * PL + y * WW + x0);
#pragma unroll
            for (int d = 0; d < 11; d++) {
                uint2 raw = *reinterpret_cast<const uint2*>(kb + (size_t)d * NPIX);
                __nv_bfloat162 lo = *reinterpret_cast<__nv_bfloat162*>(&raw.x);
                __nv_bfloat162 hi = *reinterpret_cast<__nv_bfloat162*>(&raw.y);
                float2 f01 = __bfloat1622float2(lo);
                float2 f23 = __bfloat1622float2(hi);
                t2a[0] = fmaf(f01.x, s[d][0], t2a[0]);
                t2a[1] = fmaf(f01.y, s[d][1], t2a[1]);
                t2a[2] = fmaf(f23.x, s[d][2], t2a[2]);
                t2a[3] = fmaf(f23.y, s[d][3], t2a[3]);
            }
        }
    }

    float v = (t2a[0] + t2a[1]) + (t2a[2] + t2a[3]);
#pragma unroll
    for (int s = 16; s > 0; s >>= 1) v += __shfl_down_sync(0xFFFFFFFFu, v, s);

    __shared__ float ws[4];
    int lane = threadIdx.x & 31, warp = threadIdx.x >> 5;
    if (lane == 0) ws[warp] = v;
    __syncthreads();
    if (threadIdx.x == 0) {
        float bs = (ws[0] + ws[1]) + (ws[2] + ws[3]);
        atomicAdd(&g_acc, -(double)bs);
        __threadfence();
        unsigned old = atomicAdd(&g_cnt, 1u);
        if (old == (unsigned)(NBLK_B - 1)) {
            double tot = atomicAdd(&g_acc, 0.0);
            out[0] = (float)(tot / (double)(NIMG * HH * WW));
            g_acc = 0.0;   // self-reset for next graph replay
            g_cnt = 0u;
        }
    }
}

extern "C" void kernel_launch(void* const* d_in, const int* in_sizes, int n_in,
                              void* d_out, int out_size) {
    const float* y   = (const float*)d_in[0];
    const float* rgb = (const float*)d_in[1];
    if (n_in >= 2 && in_sizes[0] == NIMG * 3 * 256 * 256) {
        const float* t = y; y = rgb; rgb = t;
    }

    const int pairs = NIMG * 3 * PL / 2;
    prep_kernel<<<(pairs + 127) / 128, 128>>>((const float4*)rgb);

    dim3 gA(NIMG * HH, 4);
    phaseA_kernel<<<gA, 128>>>();

    dim3 gB(64, 3, 2);
    phaseB_kernel<<<gB, 128>>>(y, (float*)d_out);
}

// round 4
// speedup vs baseline: 1.6277x; 1.0017x over previous
#include <cuda_runtime.h>

#define HH 128
#define WW 128
#define NIMG 2
#define NC 21
#define PL (HH * WW)
#define NBLK (2 * HH * NIMG)   // 512 blocks: (xhalf, y, n)

__device__ double   g_acc;     // zero-initialized at module load; self-resets
__device__ unsigned g_cnt;

// ---------------------------------------------------------------------------
// ONE fused kernel. Block = half-row (64 px) of one image.
//   Phase 1: 2x2 mean-pool rgb (x10 scale) rows y..y+5 + x-halo -> smem
//   Phase 2: K2[66][64] = 2*txy*(0.9*exp(-0.5|drgb|^2)+0.1) -> smem
//            (non-forward / OOB slots = 0); accumulate term1 (+ OOB closed form)
//   Phase 3: term2 via s-matrix over Y windows, K2 read back from smem
//   Epilogue: block reduce (t1 - t2), atomic, last-block finalize.
// ---------------------------------------------------------------------------
__global__ void __launch_bounds__(128) crf_fused(const float* __restrict__ Y,
                                                 const float* __restrict__ rgb,
                                                 float* __restrict__ out) {
    const int xh = blockIdx.x;           // 0..1
    const int y  = blockIdx.y;           // 0..127
    const int n  = blockIdx.z;           // 0..1
    const int x0base = xh * 64;
    const int tid = threadIdx.x;

    __shared__ float pool[6][3][80];     // pooled rgb, cols x0base-8 .. x0base+71
    __shared__ float K2s[66][64];        // slot = r*11 + (dx+5)
    __shared__ float red[4];

    // ---------------- Phase 1: pooling ----------------
    {
        const float* rbase = rgb + (size_t)n * 3 * 256 * 256;
        for (int idx = tid; idx < 6 * 3 * 80; idx += 128) {
            int ci = idx % 80;
            int ch = (idx / 80) % 3;
            int rr = idx / 240;
            int cg = x0base - 8 + ci;
            int cc = min(max(cg, 0), 127);          // clamp (unused values garbage-safe)
            int ry = min(y + rr, 127);
            const float* p = rbase + (size_t)ch * (256 * 256) + (2 * ry) * 256 + 2 * cc;
            float2 a = __ldg((const float2*)p);
            float2 b = __ldg((const float2*)(p + 256));
            pool[rr][ch][ci] = (a.x + a.y + b.x + b.y) * 2.5f;   // 0.25 mean * 10
        }
    }
    __syncthreads();

    // ---------------- Phase 2: K2 + term1 ----------------
    float t1 = 0.0f;
    {
        const int px = tid & 63;
        const int g  = tid >> 6;          // slot group 0/1
        const int x  = x0base + px;
        const int c0 = px + 8;

        const float r0 = pool[0][0][c0];
        const float g0 = pool[0][1][c0];
        const float b0 = pool[0][2][c0];

#pragma unroll
        for (int i = 0; i < 33; i++) {
            int s  = g * 33 + i;          // 0..65
            int r  = s / 11;
            int d  = s % 11;
            int dx = d - 5;
            bool fwd = (r > 0) || (dx > 0);
            bool ok  = fwd && (y + r < HH) && ((unsigned)(x + dx) < (unsigned)WW);
            float k2 = 0.0f;
            if (ok) {
                int ci = c0 + dx;
                float dr = pool[r][0][ci] - r0;
                float dg = pool[r][1][ci] - g0;
                float db = pool[r][2][ci] - b0;
                float e   = __expf(-0.5f * (dr * dr + dg * dg + db * db));
                float exy = __expf((float)(dx * dx + r * r) * (-1.0f / 72.0f));
                k2 = exy * (1.8f * e + 0.2f);     // 2 * txy * (0.9 e + 0.1)
            }
            t1 += k2;
            K2s[s][px] = k2;
        }

        if (g == 0) {  // OOB (zero-padded feature) taps, closed form, once per px
            int xl = max(x - 5, 0), xr = min(x + 5, WW - 1);
            int yl = max(y - 5, 0), yr = min(y + 5, HH - 1);
            float oob = 121.0f - (float)((xr - xl + 1) * (yr - yl + 1));
            float ep  = __expf((float)(x * x + y * y) * (-1.0f / 72.0f));
            float ec  = __expf(-0.5f * (r0 * r0 + g0 * g0 + b0 * b0));
            t1 += oob * ep * (0.9f * ec + 0.1f);
        }
    }
    __syncthreads();

    // ---------------- Phase 3: term2 (s-matrix) ----------------
    float t2 = 0.0f;
    if (tid < 112) {                       // 7 channel-groups x 16 quads
        const int cg = tid / 16;           // 0..6 -> channels 3cg..3cg+2
        const int q  = tid % 16;
        const int x0 = x0base + 4 * q;

        const float* ybase = Y + (size_t)n * NC * PL + (size_t)cg * 3 * PL;
        const bool pm2 = (x0 >= 8), pm1 = (x0 >= 4);
        const bool pp1 = (x0 <= 120), pp2 = (x0 <= 116);
        const float4 Z4 = {0.f, 0.f, 0.f, 0.f};

        float yp[3][4];
#pragma unroll
        for (int c = 0; c < 3; c++) {
            float4 v = __ldg((const float4*)(ybase + (size_t)c * PL + y * WW + x0));
            yp[c][0] = v.x; yp[c][1] = v.y; yp[c][2] = v.z; yp[c][3] = v.w;
        }

        float t2a[4] = {0.f, 0.f, 0.f, 0.f};
#pragma unroll
        for (int r = 0; r < 6; r++) {
            if (y + r < HH) {
                float s[11][4];
#pragma unroll
                for (int d = 0; d < 11; d++)
#pragma unroll
                    for (int p = 0; p < 4; p++) s[d][p] = 0.f;

#pragma unroll
                for (int c = 0; c < 3; c++) {
                    const float* rb = ybase + (size_t)c * PL + (y + r) * WW + x0;
                    float w[20];
                    float4 v;
                    v = pm2 ? __ldg((const float4*)(rb - 8)) : Z4;
                    w[0] = v.x; w[1] = v.y; w[2] = v.z; w[3] = v.w;
                    v = pm1 ? __ldg((const float4*)(rb - 4)) : Z4;
                    w[4] = v.x; w[5] = v.y; w[6] = v.z; w[7] = v.w;
                    v = __ldg((const float4*)rb);
                    w[8] = v.x; w[9] = v.y; w[10] = v.z; w[11] = v.w;
                    v = pp1 ? __ldg((const float4*)(rb + 4)) : Z4;
                    w[12] = v.x; w[13] = v.y; w[14] = v.z; w[15] = v.w;
                    v = pp2 ? __ldg((const float4*)(rb + 8)) : Z4;
                    w[16] = v.x; w[17] = v.y; w[18] = v.z; w[19] = v.w;

#pragma unroll
                    for (int d = 0; d < 11; d++)
#pragma unroll
                        for (int p = 0; p < 4; p++)
                            s[d][p] = fmaf(yp[c][p], w[3 + p + d], s[d][p]);
                }

#pragma unroll
                for (int d = 0; d < 11; d++) {
                    const float4 kv = *reinterpret_cast<const float4*>(&K2s[r * 11 + d][4 * q]);
                    t2a[0] = fmaf(kv.x, s[d][0], t2a[0]);
                    t2a[1] = fmaf(kv.y, s[d][1], t2a[1]);
                    t2a[2] = fmaf(kv.z, s[d][2], t2a[2]);
                    t2a[3] = fmaf(kv.w, s[d][3], t2a[3]);
                }
            }
        }
        t2 = (t2a[0] + t2a[1]) + (t2a[2] + t2a[3]);
    }

    // ---------------- Epilogue: reduce + finalize ----------------
    float v = t1 - t2;
#pragma unroll
    for (int sft = 16; sft > 0; sft >>= 1)
        v += __shfl_down_sync(0xFFFFFFFFu, v, sft);

    int lane = tid & 31, warp = tid >> 5;
    if (lane == 0) red[warp] = v;
    __syncthreads();
    if (tid == 0) {
        float bs = (red[0] + red[1]) + (red[2] + red[3]);
        atomicAdd(&g_acc, (double)bs);
        __threadfence();
        unsigned old = atomicAdd(&g_cnt, 1u);
        if (old == (unsigned)(NBLK - 1)) {
            double tot = atomicAdd(&g_acc, 0.0);
            out[0] = (float)(tot / (double)(NIMG * HH * WW));
            g_acc = 0.0;   // self-reset for next graph replay
            g_cnt = 0u;
        }
    }
}

extern "C" void kernel_launch(void* const* d_in, const int* in_sizes, int n_in,
                              void* d_out, int out_size) {
    const float* y   = (const float*)d_in[0];
    const float* rgb = (const float*)d_in[1];
    if (n_in >= 2 && in_sizes[0] == NIMG * 3 * 256 * 256) {
        const float* t = y; y = rgb; rgb = t;
    }

    dim3 grid(2, HH, NIMG);   // 512 blocks
    crf_fused<<<grid, 128>>>(y, rgb, (float*)d_out);
}

// round 5
// speedup vs baseline: 1.6869x; 1.0363x over previous
#include <cuda_runtime.h>

#define HH 128
#define WW 128
#define NIMG 2
#define NC 21
#define PL (HH * WW)
#define NBLK (4 * HH * NIMG)   // 1024 blocks: (xquarter, y, n)

__device__ double   g_acc;     // zero-initialized at module load; self-resets
__device__ unsigned g_cnt;

// ---------------------------------------------------------------------------
// ONE fused kernel. Block = quarter-row (32 px) of one image, 128 threads.
//   Phase 1: 2x2 mean-pool rgb (x10) rows y..y+5 + x-halo -> smem [6][3][48]
//   Phase 2: K2[66][32] = 2*txy*(0.9*exp(-0.5|drgb|^2)+0.1) -> smem
//            (non-forward / OOB slots = 0); term1 (+ OOB closed form)
//   Phase 3: term2 via s-matrix; 112 threads = 2 rowgroups x 7 cgroups x 8 quads
//   Epilogue: block reduce (t1 - t2), atomic, last-block finalize.
// ---------------------------------------------------------------------------
__global__ void __launch_bounds__(128) crf_fused(const float* __restrict__ Y,
                                                 const float* __restrict__ rgb,
                                                 float* __restrict__ out) {
    const int xq = blockIdx.x;           // 0..3
    const int y  = blockIdx.y;           // 0..127
    const int n  = blockIdx.z;           // 0..1
    const int x0base = xq * 32;
    const int tid = threadIdx.x;

    __shared__ float pool[6][3][48];     // pooled rgb, cols x0base-8 .. x0base+39
    __shared__ float K2s[66][32];        // slot = r*11 + (dx+5)
    __shared__ float red[4];

    // ---------------- Phase 1: pooling ----------------
    {
        const float* rbase = rgb + (size_t)n * 3 * 256 * 256;
#pragma unroll
        for (int it = 0; it < 7; it++) {
            int idx = it * 128 + tid;
            if (idx < 6 * 3 * 48) {
                int ci = idx % 48;
                int ch = (idx / 48) % 3;
                int rr = idx / 144;
                int cc = min(max(x0base - 8 + ci, 0), 127);   // clamp; garbage-safe
                int ry = min(y + rr, 127);
                const float* p = rbase + (size_t)ch * (256 * 256) + (2 * ry) * 256 + 2 * cc;
                float2 a = __ldg((const float2*)p);
                float2 b = __ldg((const float2*)(p + 256));
                pool[rr][ch][ci] = (a.x + a.y + b.x + b.y) * 2.5f;  // 0.25 mean * 10
            }
        }
    }
    __syncthreads();

    // ---------------- Phase 2: K2 + term1 ----------------
    float t1 = 0.0f;
    {
        const int px = tid & 31;
        const int g  = tid >> 5;          // slot group 0..3 (17 slots each, clip 66)
        const int x  = x0base + px;
        const int c0 = px + 8;

        const float r0 = pool[0][0][c0];
        const float g0 = pool[0][1][c0];
        const float b0 = pool[0][2][c0];

#pragma unroll
        for (int i = 0; i < 17; i++) {
            int s = g * 17 + i;           // 0..67
            if (s < 66) {
                int r  = s / 11;
                int dx = s % 11 - 5;
                bool fwd = (r > 0) || (dx > 0);
                bool ok  = fwd && (y + r < HH) && ((unsigned)(x + dx) < (unsigned)WW);
                float k2 = 0.0f;
                if (ok) {
                    int ci = c0 + dx;
                    float dr = pool[r][0][ci] - r0;
                    float dg = pool[r][1][ci] - g0;
                    float db = pool[r][2][ci] - b0;
                    float e   = __expf(-0.5f * (dr * dr + dg * dg + db * db));
                    float exy = __expf((float)(dx * dx + r * r) * (-1.0f / 72.0f));
                    k2 = exy * (1.8f * e + 0.2f);   // 2 * txy * (0.9 e + 0.1)
                }
                t1 += k2;
                K2s[s][px] = k2;
            }
        }

        if (g == 0) {  // OOB (zero-padded feature) taps, closed form, once per px
            int xl = max(x - 5, 0), xr = min(x + 5, WW - 1);
            int yl = max(y - 5, 0), yr = min(y + 5, HH - 1);
            float oob = 121.0f - (float)((xr - xl + 1) * (yr - yl + 1));
            float ep  = __expf((float)(x * x + y * y) * (-1.0f / 72.0f));
            float ec  = __expf(-0.5f * (r0 * r0 + g0 * g0 + b0 * b0));
            t1 += oob * ep * (0.9f * ec + 0.1f);
        }
    }
    __syncthreads();

    // ---------------- Phase 3: term2 (s-matrix) ----------------
    float t2 = 0.0f;
    if (tid < 112) {                      // 2 rowgroups x 7 cgroups x 8 quads
        const int q  = tid & 7;           // quad within 32 px
        const int cg = (tid >> 3) % 7;    // channels 3cg..3cg+2
        const int rg = tid / 56;          // rows rg*3 .. rg*3+2
        const int x0 = x0base + 4 * q;

        const float* ybase = Y + (size_t)n * NC * PL + (size_t)cg * 3 * PL;
        const bool pm2 = (x0 >= 8), pm1 = (x0 >= 4);
        const bool pp1 = (x0 <= 120), pp2 = (x0 <= 116);
        const float4 Z4 = {0.f, 0.f, 0.f, 0.f};

        float yp[3][4];
#pragma unroll
        for (int c = 0; c < 3; c++) {
            float4 v = __ldg((const float4*)(ybase + (size_t)c * PL + y * WW + x0));
            yp[c][0] = v.x; yp[c][1] = v.y; yp[c][2] = v.z; yp[c][3] = v.w;
        }

        float t2a[4] = {0.f, 0.f, 0.f, 0.f};
#pragma unroll
        for (int rr = 0; rr < 3; rr++) {
            int r = rg * 3 + rr;
            if (y + r < HH) {
                float s[11][4];
#pragma unroll
                for (int d = 0; d < 11; d++)
#pragma unroll
                    for (int p = 0; p < 4; p++) s[d][p] = 0.f;

#pragma unroll
                for (int c = 0; c < 3; c++) {
                    const float* rb = ybase + (size_t)c * PL + (y + r) * WW + x0;
                    float w[20];
                    float4 v;
                    v = pm2 ? __ldg((const float4*)(rb - 8)) : Z4;
                    w[0] = v.x; w[1] = v.y; w[2] = v.z; w[3] = v.w;
                    v = pm1 ? __ldg((const float4*)(rb - 4)) : Z4;
                    w[4] = v.x; w[5] = v.y; w[6] = v.z; w[7] = v.w;
                    v = __ldg((const float4*)rb);
                    w[8] = v.x; w[9] = v.y; w[10] = v.z; w[11] = v.w;
                    v = pp1 ? __ldg((const float4*)(rb + 4)) : Z4;
                    w[12] = v.x; w[13] = v.y; w[14] = v.z; w[15] = v.w;
                    v = pp2 ? __ldg((const float4*)(rb + 8)) : Z4;
                    w[16] = v.x; w[17] = v.y; w[18] = v.z; w[19] = v.w;

#pragma unroll
                    for (int d = 0; d < 11; d++)
#pragma unroll
                        for (int p = 0; p < 4; p++)
                            s[d][p] = fmaf(yp[c][p], w[3 + p + d], s[d][p]);
                }

#pragma unroll
                for (int d = 0; d < 11; d++) {
                    const float4 kv = *reinterpret_cast<const float4*>(&K2s[r * 11 + d][4 * q]);
                    t2a[0] = fmaf(kv.x, s[d][0], t2a[0]);
                    t2a[1] = fmaf(kv.y, s[d][1], t2a[1]);
                    t2a[2] = fmaf(kv.z, s[d][2], t2a[2]);
                    t2a[3] = fmaf(kv.w, s[d][3], t2a[3]);
                }
            }
        }
        t2 = (t2a[0] + t2a[1]) + (t2a[2] + t2a[3]);
    }

    // ---------------- Epilogue: reduce + finalize ----------------
    float v = t1 - t2;
#pragma unroll
    for (int sft = 16; sft > 0; sft >>= 1)
        v += __shfl_down_sync(0xFFFFFFFFu, v, sft);

    int lane = tid & 31, warp = tid >> 5;
    if (lane == 0) red[warp] = v;
    __syncthreads();
    if (tid == 0) {
        float bs = (red[0] + red[1]) + (red[2] + red[3]);
        atomicAdd(&g_acc, (double)bs);
        __threadfence();
        unsigned old = atomicAdd(&g_cnt, 1u);
        if (old == (unsigned)(NBLK - 1)) {
            double tot = atomicAdd(&g_acc, 0.0);
            out[0] = (float)(tot / (double)(NIMG * HH * WW));
            g_acc = 0.0;   // self-reset for next graph replay
            g_cnt = 0u;
        }
    }
}

extern "C" void kernel_launch(void* const* d_in, const int* in_sizes, int n_in,
                              void* d_out, int out_size) {
    const float* y   = (const float*)d_in[0];
    const float* rgb = (const float*)d_in[1];
    if (n_in >= 2 && in_sizes[0] == NIMG * 3 * 256 * 256) {
        const float* t = y; y = rgb; rgb = t;
    }

    dim3 grid(4, HH, NIMG);   // 1024 blocks
    crf_fused<<<grid, 128>>>(y, rgb, (float*)d_out);
}

// round 6
// speedup vs baseline: 1.8190x; 1.0784x over previous
#include <cuda_runtime.h>

#define HH 128
#define WW 128
#define NIMG 2
#define NC 21
#define PL (HH * WW)
#define NBLK (4 * HH * NIMG)   // 1024 blocks: (xquarter, y, n)

__device__ double   g_acc;     // zero-initialized at module load; self-resets
__device__ unsigned g_cnt;

// exp(-k^2/72) for k = 0..5 (compile-time folded)
__device__ __forceinline__ constexpr float exy_tab(int k) {
    constexpr float E[6] = {1.0f, 0.98620712f, 0.94595947f,
                            0.88249690f, 0.80073740f, 0.70664828f};
    return E[k];
}

// ---------------------------------------------------------------------------
// Phase-2 worker: warp-group G handles slots with slot%4 == G.
// Everything (r, dx, slot, exy) is compile-time; only bounds + rgb are runtime.
// Non-forward slots are written as 0 (phase 3 multiplies by them blindly).
// ---------------------------------------------------------------------------
template <int G>
__device__ __forceinline__ float phase2_slots(const float (*pool)[3][48],
                                              float (*K2s)[32],
                                              int px, int x, int y) {
    const int c0 = px + 8;
    const float r0 = pool[0][0][c0];
    const float g0 = pool[0][1][c0];
    const float b0 = pool[0][2][c0];
    float t1 = 0.0f;
#pragma unroll
    for (int r = 0; r <= 5; r++) {
#pragma unroll
        for (int dxi = 0; dxi < 11; dxi++) {
            const int slot = r * 11 + dxi;
            if ((slot & 3) == G) {
                const int dx = dxi - 5;
                const bool fwd = (r > 0) || (dx > 0);
                float k2 = 0.0f;
                if (fwd && (y + r < HH) && ((unsigned)(x + dx) < (unsigned)WW)) {
                    const float exy = exy_tab(r) * exy_tab(dx < 0 ? -dx : dx);
                    const int ci = c0 + dx;
                    float dr = pool[r][0][ci] - r0;
                    float dg = pool[r][1][ci] - g0;
                    float db = pool[r][2][ci] - b0;
                    float e  = __expf(-0.5f * (dr * dr + dg * dg + db * db));
                    k2 = fmaf(1.8f * exy, e, 0.2f * exy);
                }
                t1 += k2;
                K2s[slot][px] = k2;
            }
        }
    }
    return t1;
}

// ---------------------------------------------------------------------------
// ONE fused kernel. Block = quarter-row (32 px), 128 threads.
// ---------------------------------------------------------------------------
__global__ void __launch_bounds__(128, 6) crf_fused(const float* __restrict__ Y,
                                                    const float* __restrict__ rgb,
                                                    float* __restrict__ out) {
    const int xq = blockIdx.x;           // 0..3
    const int y  = blockIdx.y;           // 0..127
    const int n  = blockIdx.z;           // 0..1
    const int x0base = xq * 32;
    const int tid = threadIdx.x;

    __shared__ float pool[6][3][48];     // pooled rgb, cols x0base-8 .. x0base+39
    __shared__ float K2s[66][32];        // slot = r*11 + (dx+5)
    __shared__ float red[4];

    // ---------------- Phase 1: 2x2 mean pool (x10 scale) ----------------
    {
        const float* rbase = rgb + (size_t)n * 3 * 256 * 256;
#pragma unroll
        for (int it = 0; it < 7; it++) {
            int idx = it * 128 + tid;
            if (idx < 6 * 3 * 48) {
                int ci = idx % 48;
                int ch = (idx / 48) % 3;
                int rr = idx / 144;
                int cc = min(max(x0base - 8 + ci, 0), 127);   // clamp; garbage-safe
                int ry = min(y + rr, 127);
                const float* p = rbase + (size_t)ch * (256 * 256) + (2 * ry) * 256 + 2 * cc;
                float2 a = __ldg((const float2*)p);
                float2 b = __ldg((const float2*)(p + 256));
                pool[rr][ch][ci] = (a.x + a.y + b.x + b.y) * 2.5f;  // 0.25 mean * 10
            }
        }
    }
    __syncthreads();

    // ---------------- Phase 2: K2 + term1 ----------------
    float t1;
    {
        const int px = tid & 31;
        const int g  = tid >> 5;          // warp-uniform
        const int x  = x0base + px;

        if      (g == 0) t1 = phase2_slots<0>(pool, K2s, px, x, y);
        else if (g == 1) t1 = phase2_slots<1>(pool, K2s, px, x, y);
        else if (g == 2) t1 = phase2_slots<2>(pool, K2s, px, x, y);
        else             t1 = phase2_slots<3>(pool, K2s, px, x, y);

        if (g == 0) {  // OOB (zero-padded feature) taps, closed form, once per px
            const int c0 = px + 8;
            float r0 = pool[0][0][c0], g0 = pool[0][1][c0], b0 = pool[0][2][c0];
            int xl = max(x - 5, 0), xr = min(x + 5, WW - 1);
            int yl = max(y - 5, 0), yr = min(y + 5, HH - 1);
            float oob = 121.0f - (float)((xr - xl + 1) * (yr - yl + 1));
            float ep  = __expf((float)(x * x + y * y) * (-1.0f / 72.0f));
            float ec  = __expf(-0.5f * (r0 * r0 + g0 * g0 + b0 * b0));
            t1 += oob * ep * (0.9f * ec + 0.1f);
        }
    }
    __syncthreads();

    // ---------------- Phase 3: term2 (s-matrix) ----------------
    float t2 = 0.0f;
    if (tid < 112) {                      // 2 rowgroups x 7 cgroups x 8 quads
        const int q  = tid & 7;           // quad within 32 px
        const int cg = (tid >> 3) % 7;    // channels 3cg..3cg+2
        const int rg = tid / 56;          // rows rg*3 .. rg*3+2
        const int x0 = x0base + 4 * q;

        const float* ybase = Y + (size_t)n * NC * PL + (size_t)cg * 3 * PL;
        const bool pm2 = (x0 >= 8), pm1 = (x0 >= 4);
        const bool pp1 = (x0 <= 120), pp2 = (x0 <= 116);
        const float4 Z4 = {0.f, 0.f, 0.f, 0.f};

        float yp[3][4];
#pragma unroll
        for (int c = 0; c < 3; c++) {
            float4 v = __ldg((const float4*)(ybase + (size_t)c * PL + y * WW + x0));
            yp[c][0] = v.x; yp[c][1] = v.y; yp[c][2] = v.z; yp[c][3] = v.w;
        }

        float t2a[4] = {0.f, 0.f, 0.f, 0.f};
#pragma unroll
        for (int rr = 0; rr < 3; rr++) {
            int r = rg * 3 + rr;
            if (y + r < HH) {
                float s[11][4];
#pragma unroll
                for (int d = 0; d < 11; d++)
#pragma unroll
                    for (int p = 0; p < 4; p++) s[d][p] = 0.f;

#pragma unroll
                for (int c = 0; c < 3; c++) {
                    const float* rb = ybase + (size_t)c * PL + (y + r) * WW + x0;
                    float w[20];
                    float4 v;
                    v = pm2 ? __ldg((const float4*)(rb - 8)) : Z4;
                    w[0] = v.x; w[1] = v.y; w[2] = v.z; w[3] = v.w;
                    v = pm1 ? __ldg((const float4*)(rb - 4)) : Z4;
                    w[4] = v.x; w[5] = v.y; w[6] = v.z; w[7] = v.w;
                    v = __ldg((const float4*)rb);
                    w[8] = v.x; w[9] = v.y; w[10] = v.z; w[11] = v.w;
                    v = pp1 ? __ldg((const float4*)(rb + 4)) : Z4;
                    w[12] = v.x; w[13] = v.y; w[14] = v.z; w[15] = v.w;
                    v = pp2 ? __ldg((const float4*)(rb + 8)) : Z4;
                    w[16] = v.x; w[17] = v.y; w[18] = v.z; w[19] = v.w;

#pragma unroll
                    for (int d = 0; d < 11; d++)
#pragma unroll
                        for (int p = 0; p < 4; p++)
                            s[d][p] = fmaf(yp[c][p], w[3 + p + d], s[d][p]);
                }

#pragma unroll
                for (int d = 0; d < 11; d++) {
                    const float4 kv = *reinterpret_cast<const float4*>(&K2s[r * 11 + d][4 * q]);
                    t2a[0] = fmaf(kv.x, s[d][0], t2a[0]);
                    t2a[1] = fmaf(kv.y, s[d][1], t2a[1]);
                    t2a[2] = fmaf(kv.z, s[d][2], t2a[2]);
                    t2a[3] = fmaf(kv.w, s[d][3], t2a[3]);
                }
            }
        }
        t2 = (t2a[0] + t2a[1]) + (t2a[2] + t2a[3]);
    }

    // ---------------- Epilogue: reduce + finalize ----------------
    float v = t1 - t2;
#pragma unroll
    for (int sft = 16; sft > 0; sft >>= 1)
        v += __shfl_down_sync(0xFFFFFFFFu, v, sft);

    int lane = tid & 31, warp = tid >> 5;
    if (lane == 0) red[warp] = v;
    __syncthreads();
    if (tid == 0) {
        float bs = (red[0] + red[1]) + (red[2] + red[3]);
        atomicAdd(&g_acc, (double)bs);
        __threadfence();
        unsigned old = atomicAdd(&g_cnt, 1u);
        if (old == (unsigned)(NBLK - 1)) {
            double tot = atomicAdd(&g_acc, 0.0);
            out[0] = (float)(tot / (double)(NIMG * HH * WW));
            g_acc = 0.0;   // self-reset for next graph replay
            g_cnt = 0u;
        }
    }
}

extern "C" void kernel_launch(void* const* d_in, const int* in_sizes, int n_in,
                              void* d_out, int out_size) {
    const float* y   = (const float*)d_in[0];
    const float* rgb = (const float*)d_in[1];
    if (n_in >= 2 && in_sizes[0] == NIMG * 3 * 256 * 256) {
        const float* t = y; y = rgb; rgb = t;
    }

    dim3 grid(4, HH, NIMG);   // 1024 blocks
    crf_fused<<<grid, 128>>>(y, rgb, (float*)d_out);
}

// round 7
// speedup vs baseline: 1.8224x; 1.0019x over previous
#include <cuda_runtime.h>

#define HH 128
#define WW 128
#define NIMG 2
#define NC 21
#define PL (HH * WW)
#define NBLK (4 * HH * NIMG)   // 1024 blocks: (xquarter, y, n)

__device__ double   g_accs[32];   // spread accumulators (zero-init; self-reset)
__device__ unsigned g_cnt;

// exp(-k^2/72) for k = 0..5 (compile-time folded)
__device__ __forceinline__ constexpr float exy_tab(int k) {
    constexpr float E[6] = {1.0f, 0.98620712f, 0.94595947f,
                            0.88249690f, 0.80073740f, 0.70664828f};
    return E[k];
}

// ---------------------------------------------------------------------------
// Phase-2 worker: warp-group G handles slots with slot%4 == G.
// (r, dx, slot, exy) compile-time. Non-forward slots written 0.
// ---------------------------------------------------------------------------
template <int G>
__device__ __forceinline__ float phase2_slots(const float (*pool)[3][48],
                                              float (*K2s)[32],
                                              int px, int x, int y) {
    const int c0 = px + 8;
    const float r0 = pool[0][0][c0];
    const float g0 = pool[0][1][c0];
    const float b0 = pool[0][2][c0];
    float t1 = 0.0f;
#pragma unroll
    for (int r = 0; r <= 5; r++) {
#pragma unroll
        for (int dxi = 0; dxi < 11; dxi++) {
            const int slot = r * 11 + dxi;
            if ((slot & 3) == G) {
                const int dx = dxi - 5;
                const bool fwd = (r > 0) || (dx > 0);
                float k2 = 0.0f;
                if (fwd && (y + r < HH) && ((unsigned)(x + dx) < (unsigned)WW)) {
                    const float exy = exy_tab(r) * exy_tab(dx < 0 ? -dx : dx);
                    const int ci = c0 + dx;
                    float dr = pool[r][0][ci] - r0;
                    float dg = pool[r][1][ci] - g0;
                    float db = pool[r][2][ci] - b0;
                    float e  = __expf(-0.5f * (dr * dr + dg * dg + db * db));
                    k2 = fmaf(1.8f * exy, e, 0.2f * exy);
                }
                t1 += k2;
                K2s[slot][px] = k2;
            }
        }
    }
    return t1;
}

// ---------------------------------------------------------------------------
// ONE fused kernel. Block = quarter-row (32 px), 128 threads, 7 blocks/SM
// -> 1036 CTA capacity >= 1024 grid: SINGLE WAVE.
// ---------------------------------------------------------------------------
__global__ void __launch_bounds__(128, 7) crf_fused(const float* __restrict__ Y,
                                                    const float* __restrict__ rgb,
                                                    float* __restrict__ out) {
    const int xq = blockIdx.x;           // 0..3
    const int y  = blockIdx.y;           // 0..127
    const int n  = blockIdx.z;           // 0..1
    const int x0base = xq * 32;
    const int tid = threadIdx.x;

    __shared__ float pool[6][3][48];     // pooled rgb, cols x0base-8 .. x0base+39
    __shared__ float K2s[66][32];        // slot = r*11 + (dx+5)
    __shared__ float red[4];

    // ---------------- Phase 1: 2x2 mean pool (x10 scale) ----------------
    {
        const float* rbase = rgb + (size_t)n * 3 * 256 * 256;
#pragma unroll
        for (int it = 0; it < 7; it++) {
            int idx = it * 128 + tid;
            if (idx < 6 * 3 * 48) {
                int ci = idx % 48;
                int ch = (idx / 48) % 3;
                int rr = idx / 144;
                int cc = min(max(x0base - 8 + ci, 0), 127);   // clamp; garbage-safe
                int ry = min(y + rr, 127);
                const float* p = rbase + (size_t)ch * (256 * 256) + (2 * ry) * 256 + 2 * cc;
                float2 a = __ldg((const float2*)p);
                float2 b = __ldg((const float2*)(p + 256));
                pool[rr][ch][ci] = (a.x + a.y + b.x + b.y) * 2.5f;  // 0.25 mean * 10
            }
        }
    }
    __syncthreads();

    // ---------------- Phase 2: K2 + term1 ----------------
    float t1;
    {
        const int px = tid & 31;
        const int g  = tid >> 5;          // warp-uniform
        const int x  = x0base + px;

        if      (g == 0) t1 = phase2_slots<0>(pool, K2s, px, x, y);
        else if (g == 1) t1 = phase2_slots<1>(pool, K2s, px, x, y);
        else if (g == 2) t1 = phase2_slots<2>(pool, K2s, px, x, y);
        else             t1 = phase2_slots<3>(pool, K2s, px, x, y);

        if (g == 0) {  // OOB (zero-padded feature) taps, closed form, once per px
            const int c0 = px + 8;
            float r0 = pool[0][0][c0], g0 = pool[0][1][c0], b0 = pool[0][2][c0];
            int xl = max(x - 5, 0), xr = min(x + 5, WW - 1);
            int yl = max(y - 5, 0), yr = min(y + 5, HH - 1);
            float oob = 121.0f - (float)((xr - xl + 1) * (yr - yl + 1));
            float ep  = __expf((float)(x * x + y * y) * (-1.0f / 72.0f));
            float ec  = __expf(-0.5f * (r0 * r0 + g0 * g0 + b0 * b0));
            t1 += oob * ep * (0.9f * ec + 0.1f);
        }
    }
    __syncthreads();

    // ---------------- Phase 3: term2 (s-matrix, d split in two halves) ----
    float t2 = 0.0f;
    if (tid < 112) {                      // 2 rowgroups x 7 cgroups x 8 quads
        const int q  = tid & 7;           // quad within 32 px
        const int cg = (tid >> 3) % 7;    // channels 3cg..3cg+2
        const int rg = tid / 56;          // rows rg*3 .. rg*3+2
        const int x0 = x0base + 4 * q;

        const float* ybase = Y + (size_t)n * NC * PL + (size_t)cg * 3 * PL;
        const bool pm2 = (x0 >= 8), pm1 = (x0 >= 4);
        const bool pp1 = (x0 <= 120), pp2 = (x0 <= 116);
        const float4 Z4 = {0.f, 0.f, 0.f, 0.f};

        float yp[3][4];
#pragma unroll
        for (int c = 0; c < 3; c++) {
            float4 v = __ldg((const float4*)(ybase + (size_t)c * PL + y * WW + x0));
            yp[c][0] = v.x; yp[c][1] = v.y; yp[c][2] = v.z; yp[c][3] = v.w;
        }

        float t2a[4] = {0.f, 0.f, 0.f, 0.f};
#pragma unroll
        for (int rr = 0; rr < 3; rr++) {
            int r = rg * 3 + rr;
            if (y + r < HH) {
                const float* krow = &K2s[r * 11][0];

                // ===== half A: d = 0..4, window floats x0-8 .. x0+3 =====
                {
                    float sA[5][4];
#pragma unroll
                    for (int d = 0; d < 5; d++)
#pragma unroll
                        for (int p = 0; p < 4; p++) sA[d][p] = 0.f;

#pragma unroll
                    for (int c = 0; c < 3; c++) {
                        const float* rb = ybase + (size_t)c * PL + (y + r) * WW + x0;
                        float w[12];
                        float4 v;
                        v = pm2 ? __ldg((const float4*)(rb - 8)) : Z4;
                        w[0] = v.x; w[1] = v.y; w[2] = v.z; w[3] = v.w;
                        v = pm1 ? __ldg((const float4*)(rb - 4)) : Z4;
                        w[4] = v.x; w[5] = v.y; w[6] = v.z; w[7] = v.w;
                        v = __ldg((const float4*)rb);
                        w[8] = v.x; w[9] = v.y; w[10] = v.z; w[11] = v.w;
                        // original index 3+p+d (d=0..4) -> 3..10, fits w[0..11]
#pragma unroll
                        for (int d = 0; d < 5; d++)
#pragma unroll
                            for (int p = 0; p < 4; p++)
                                sA[d][p] = fmaf(yp[c][p], w[3 + p + d], sA[d][p]);
                    }
#pragma unroll
                    for (int d = 0; d < 5; d++) {
                        const float4 kv = *reinterpret_cast<const float4*>(krow + d * 32 + 4 * q);
                        t2a[0] = fmaf(kv.x, sA[d][0], t2a[0]);
                        t2a[1] = fmaf(kv.y, sA[d][1], t2a[1]);
                        t2a[2] = fmaf(kv.z, sA[d][2], t2a[2]);
                        t2a[3] = fmaf(kv.w, sA[d][3], t2a[3]);
                    }
                }

                // ===== half B: d = 5..10, window floats x0 .. x0+11 =====
                {
                    float sB[6][4];
#pragma unroll
                    for (int d = 0; d < 6; d++)
#pragma unroll
                        for (int p = 0; p < 4; p++) sB[d][p] = 0.f;

#pragma unroll
                    for (int c = 0; c < 3; c++) {
                        const float* rb = ybase + (size_t)c * PL + (y + r) * WW + x0;
                        float w[12];
                        float4 v;
                        v = __ldg((const float4*)rb);
                        w[0] = v.x; w[1] = v.y; w[2] = v.z; w[3] = v.w;
                        v = pp1 ? __ldg((const float4*)(rb + 4)) : Z4;
                        w[4] = v.x; w[5] = v.y; w[6] = v.z; w[7] = v.w;
                        v = pp2 ? __ldg((const float4*)(rb + 8)) : Z4;
                        w[8] = v.x; w[9] = v.y; w[10] = v.z; w[11] = v.w;
                        // original index 3+p+d - 8 = p+d-5 (d=5..10) -> 0..8
#pragma unroll
                        for (int d = 5; d < 11; d++)
#pragma unroll
                            for (int p = 0; p < 4; p++)
                                sB[d - 5][p] = fmaf(yp[c][p], w[p + d - 5], sB[d - 5][p]);
                    }
#pragma unroll
                    for (int d = 5; d < 11; d++) {
                        const float4 kv = *reinterpret_cast<const float4*>(krow + d * 32 + 4 * q);
                        t2a[0] = fmaf(kv.x, sB[d - 5][0], t2a[0]);
                        t2a[1] = fmaf(kv.y, sB[d - 5][1], t2a[1]);
                        t2a[2] = fmaf(kv.z, sB[d - 5][2], t2a[2]);
                        t2a[3] = fmaf(kv.w, sB[d - 5][3], t2a[3]);
                    }
                }
            }
        }
        t2 = (t2a[0] + t2a[1]) + (t2a[2] + t2a[3]);
    }

    // ---------------- Epilogue: reduce + finalize ----------------
    float v = t1 - t2;
#pragma unroll
    for (int sft = 16; sft > 0; sft >>= 1)
        v += __shfl_down_sync(0xFFFFFFFFu, v, sft);

    int lane = tid & 31, warp = tid >> 5;
    if (lane == 0) red[warp] = v;
    __syncthreads();
    if (tid == 0) {
        float bs = (red[0] + red[1]) + (red[2] + red[3]);
        int slot = ((blockIdx.y & 7) << 2) | blockIdx.x;   // 32 spread slots
        atomicAdd(&g_accs[slot], (double)bs);
        __threadfence();
        unsigned old = atomicAdd(&g_cnt, 1u);
        if (old == (unsigned)(NBLK - 1)) {
            double tot = 0.0;
#pragma unroll
            for (int i = 0; i < 32; i++) {
                tot += atomicAdd(&g_accs[i], 0.0);
                g_accs[i] = 0.0;                 // self-reset for graph replay
            }
            out[0] = (float)(tot / (double)(NIMG * HH * WW));
            g_cnt = 0u;
        }
    }
}

extern "C" void kernel_launch(void* const* d_in, const int* in_sizes, int n_in,
                              void* d_out, int out_size) {
    const float* y   = (const float*)d_in[0];
    const float* rgb = (const float*)d_in[1];
    if (n_in >= 2 && in_sizes[0] == NIMG * 3 * 256 * 256) {
        const float* t = y; y = rgb; rgb = t;
    }

    dim3 grid(4, HH, NIMG);   // 1024 blocks, single wave at 7 blocks/SM
    crf_fused<<<grid, 128>>>(y, rgb, (float*)d_out);
}

// round 8
// speedup vs baseline: 1.8466x; 1.0133x over previous
#include <cuda_runtime.h>

#define HH 128
#define WW 128
#define NIMG 2
#define NC 21
#define PL (HH * WW)
#define NBLK (4 * HH * NIMG)   // 1024 blocks: (xquarter, y, n)

__device__ double   g_accs[32];   // spread accumulators (zero-init; self-reset)
__device__ unsigned g_cnt;

typedef unsigned long long u64;

// ---- packed f32x2 helpers (FFMA2 path; ptxas never emits these from C++) ----
__device__ __forceinline__ u64 pk(float lo, float hi) {
    u64 r;
    asm("mov.b64 %0, {%1, %2};" : "=l"(r) : "f"(lo), "f"(hi));
    return r;
}
__device__ __forceinline__ void fma2(u64& d, u64 a, u64 b) {
    asm("fma.rn.f32x2 %0, %1, %2, %0;" : "+l"(d) : "l"(a), "l"(b));
}
__device__ __forceinline__ float2 unpk(u64 v) {
    float lo, hi;
    asm("mov.b64 {%0, %1}, %2;" : "=f"(lo), "=f"(hi) : "l"(v));
    return make_float2(lo, hi);
}

// exp(-k^2/72) for k = 0..5 (compile-time folded)
__device__ __forceinline__ constexpr float exy_tab(int k) {
    constexpr float E[6] = {1.0f, 0.98620712f, 0.94595947f,
                            0.88249690f, 0.80073740f, 0.70664828f};
    return E[k];
}

// ---------------------------------------------------------------------------
// Phase-2 worker: warp-group G handles slots with slot%4 == G.
// (r, dx, slot, exy) compile-time. Non-forward slots written 0.
// ---------------------------------------------------------------------------
template <int G>
__device__ __forceinline__ float phase2_slots(const float (*pool)[3][48],
                                              float (*K2s)[32],
                                              int px, int x, int y) {
    const int c0 = px + 8;
    const float r0 = pool[0][0][c0];
    const float g0 = pool[0][1][c0];
    const float b0 = pool[0][2][c0];
    float t1 = 0.0f;
#pragma unroll
    for (int r = 0; r <= 5; r++) {
#pragma unroll
        for (int dxi = 0; dxi < 11; dxi++) {
            const int slot = r * 11 + dxi;
            if ((slot & 3) == G) {
                const int dx = dxi - 5;
                const bool fwd = (r > 0) || (dx > 0);
                float k2 = 0.0f;
                if (fwd && (y + r < HH) && ((unsigned)(x + dx) < (unsigned)WW)) {
                    const float exy = exy_tab(r) * exy_tab(dx < 0 ? -dx : dx);
                    const int ci = c0 + dx;
                    float dr = pool[r][0][ci] - r0;
                    float dg = pool[r][1][ci] - g0;
                    float db = pool[r][2][ci] - b0;
                    float e  = __expf(-0.5f * (dr * dr + dg * dg + db * db));
                    k2 = fmaf(1.8f * exy, e, 0.2f * exy);
                }
                t1 += k2;
                K2s[slot][px] = k2;
            }
        }
    }
    return t1;
}

// ---------------------------------------------------------------------------
// ONE fused kernel. Block = quarter-row (32 px), 128 threads, 7 blocks/SM
// -> 1036 CTA capacity >= 1024 grid: SINGLE WAVE. Phase 3 in packed f32x2.
// ---------------------------------------------------------------------------
__global__ void __launch_bounds__(128, 7) crf_fused(const float* __restrict__ Y,
                                                    const float* __restrict__ rgb,
                                                    float* __restrict__ out) {
    const int xq = blockIdx.x;           // 0..3
    const int y  = blockIdx.y;           // 0..127
    const int n  = blockIdx.z;           // 0..1
    const int x0base = xq * 32;
    const int tid = threadIdx.x;

    __shared__ float pool[6][3][48];     // pooled rgb, cols x0base-8 .. x0base+39
    __shared__ float K2s[66][32];        // slot = r*11 + (dx+5)
    __shared__ float red[4];

    // ---------------- Phase 1: 2x2 mean pool (x10 scale) ----------------
    {
        const float* rbase = rgb + (size_t)n * 3 * 256 * 256;
#pragma unroll
        for (int it = 0; it < 7; it++) {
            int idx = it * 128 + tid;
            if (idx < 6 * 3 * 48) {
                int ci = idx % 48;
                int ch = (idx / 48) % 3;
                int rr = idx / 144;
                int cc = min(max(x0base - 8 + ci, 0), 127);   // clamp; garbage-safe
                int ry = min(y + rr, 127);
                const float* p = rbase + (size_t)ch * (256 * 256) + (2 * ry) * 256 + 2 * cc;
                float2 a = __ldg((const float2*)p);
                float2 b = __ldg((const float2*)(p + 256));
                pool[rr][ch][ci] = (a.x + a.y + b.x + b.y) * 2.5f;  // 0.25 mean * 10
            }
        }
    }
    __syncthreads();

    // ---------------- Phase 2: K2 + term1 ----------------
    float t1;
    {
        const int px = tid & 31;
        const int g  = tid >> 5;          // warp-uniform
        const int x  = x0base + px;

        if      (g == 0) t1 = phase2_slots<0>(pool, K2s, px, x, y);
        else if (g == 1) t1 = phase2_slots<1>(pool, K2s, px, x, y);
        else if (g == 2) t1 = phase2_slots<2>(pool, K2s, px, x, y);
        else             t1 = phase2_slots<3>(pool, K2s, px, x, y);

        if (g == 0) {  // OOB (zero-padded feature) taps, closed form, once per px
            const int c0 = px + 8;
            float r0 = pool[0][0][c0], g0 = pool[0][1][c0], b0 = pool[0][2][c0];
            int xl = max(x - 5, 0), xr = min(x + 5, WW - 1);
            int yl = max(y - 5, 0), yr = min(y + 5, HH - 1);
            float oob = 121.0f - (float)((xr - xl + 1) * (yr - yl + 1));
            float ep  = __expf((float)(x * x + y * y) * (-1.0f / 72.0f));
            float ec  = __expf(-0.5f * (r0 * r0 + g0 * g0 + b0 * b0));
            t1 += oob * ep * (0.9f * ec + 0.1f);
        }
    }
    __syncthreads();

    // ---------------- Phase 3: term2 (packed f32x2 s-matrix) ----------------
    float t2 = 0.0f;
    if (tid < 112) {                      // 2 rowgroups x 7 cgroups x 8 quads
        const int q  = tid & 7;           // quad within 32 px
        const int cg = (tid >> 3) % 7;    // channels 3cg..3cg+2
        const int rg = tid / 56;          // rows rg*3 .. rg*3+2
        const int x0 = x0base + 4 * q;

        const float* ybase = Y + (size_t)n * NC * PL + (size_t)cg * 3 * PL;
        const bool pm2 = (x0 >= 8), pm1 = (x0 >= 4);
        const bool pp1 = (x0 <= 120), pp2 = (x0 <= 116);
        const float4 Z4 = {0.f, 0.f, 0.f, 0.f};

        u64 yp01[3], yp23[3];
#pragma unroll
        for (int c = 0; c < 3; c++) {
            float4 v = __ldg((const float4*)(ybase + (size_t)c * PL + y * WW + x0));
            yp01[c] = pk(v.x, v.y);
            yp23[c] = pk(v.z, v.w);
        }

        u64 acc01 = 0ull, acc23 = 0ull;   // packed (+0,+0)

#pragma unroll
        for (int rr = 0; rr < 3; rr++) {
            int r = rg * 3 + rr;
            if (y + r < HH) {
                const float* krow = &K2s[r * 11][0] + 4 * q;

                // ===== half A: d = 0..4, window floats x0-8 .. x0+3 =====
                {
                    u64 sA[5][2];
#pragma unroll
                    for (int d = 0; d < 5; d++) { sA[d][0] = 0ull; sA[d][1] = 0ull; }

#pragma unroll
                    for (int c = 0; c < 3; c++) {
                        const float* rb = ybase + (size_t)c * PL + (y + r) * WW + x0;
                        float w[12];
                        float4 v;
                        v = pm2 ? __ldg((const float4*)(rb - 8)) : Z4;
                        w[0] = v.x; w[1] = v.y; w[2] = v.z; w[3] = v.w;
                        v = pm1 ? __ldg((const float4*)(rb - 4)) : Z4;
                        w[4] = v.x; w[5] = v.y; w[6] = v.z; w[7] = v.w;
                        v = __ldg((const float4*)rb);
                        w[8] = v.x; w[9] = v.y; w[10] = v.z; w[11] = v.w;

                        u64 P[10];
#pragma unroll
                        for (int a = 3; a <= 9; a++) P[a] = pk(w[a], w[a + 1]);

                        // scalar form: sA[d][p] += yp[c][p] * w[3+p+d]
#pragma unroll
                        for (int d = 0; d < 5; d++) {
                            fma2(sA[d][0], yp01[c], P[3 + d]);
                            fma2(sA[d][1], yp23[c], P[5 + d]);
                        }
                    }
#pragma unroll
                    for (int d = 0; d < 5; d++) {
                        const float4 kv = *reinterpret_cast<const float4*>(krow + d * 32);
                        fma2(acc01, pk(kv.x, kv.y), sA[d][0]);
                        fma2(acc23, pk(kv.z, kv.w), sA[d][1]);
                    }
                }

                // ===== half B: d = 5..10, window floats x0 .. x0+11 =====
                {
                    u64 sB[6][2];
#pragma unroll
                    for (int d = 0; d < 6; d++) { sB[d][0] = 0ull; sB[d][1] = 0ull; }

#pragma unroll
                    for (int c = 0; c < 3; c++) {
                        const float* rb = ybase + (size_t)c * PL + (y + r) * WW + x0;
                        float w[12];
                        float4 v;
                        v = __ldg((const float4*)rb);
                        w[0] = v.x; w[1] = v.y; w[2] = v.z; w[3] = v.w;
                        v = pp1 ? __ldg((const float4*)(rb + 4)) : Z4;
                        w[4] = v.x; w[5] = v.y; w[6] = v.z; w[7] = v.w;
                        v = pp2 ? __ldg((const float4*)(rb + 8)) : Z4;
                        w[8] = v.x; w[9] = v.y; w[10] = v.z; w[11] = v.w;

                        u64 P[8];
#pragma unroll
                        for (int a = 0; a <= 7; a++) P[a] = pk(w[a], w[a + 1]);

                        // scalar form: sB[d-5][p] += yp[c][p] * w[p+d-5]
#pragma unroll
                        for (int d = 5; d < 11; d++) {
                            fma2(sB[d - 5][0], yp01[c], P[d - 5]);
                            fma2(sB[d - 5][1], yp23[c], P[d - 3]);
                        }
                    }
#pragma unroll
                    for (int d = 5; d < 11; d++) {
                        const float4 kv = *reinterpret_cast<const float4*>(krow + d * 32);
                        fma2(acc01, pk(kv.x, kv.y), sB[d - 5][0]);
                        fma2(acc23, pk(kv.z, kv.w), sB[d - 5][1]);
                    }
                }
            }
        }
        float2 a01 = unpk(acc01);
        float2 a23 = unpk(acc23);
        t2 = (a01.x + a01.y) + (a23.x + a23.y);
    }

    // ---------------- Epilogue: reduce + finalize ----------------
    float v = t1 - t2;
#pragma unroll
    for (int sft = 16; sft > 0; sft >>= 1)
        v += __shfl_down_sync(0xFFFFFFFFu, v, sft);

    int lane = tid & 31, warp = tid >> 5;
    if (lane == 0) red[warp] = v;
    __syncthreads();
    if (tid == 0) {
        float bs = (red[0] + red[1]) + (red[2] + red[3]);
        int slot = ((blockIdx.y & 7) << 2) | blockIdx.x;   // 32 spread slots
        atomicAdd(&g_accs[slot], (double)bs);
        __threadfence();
        unsigned old = atomicAdd(&g_cnt, 1u);
        if (old == (unsigned)(NBLK - 1)) {
            double tot = 0.0;
#pragma unroll
            for (int i = 0; i < 32; i++) {
                tot += atomicAdd(&g_accs[i], 0.0);
                g_accs[i] = 0.0;                 // self-reset for graph replay
            }
            out[0] = (float)(tot / (double)(NIMG * HH * WW));
            g_cnt = 0u;
        }
    }
}

extern "C" void kernel_launch(void* const* d_in, const int* in_sizes, int n_in,
                              void* d_out, int out_size) {
    const float* y   = (const float*)d_in[0];
    const float* rgb = (const float*)d_in[1];
    if (n_in >= 2 && in_sizes[0] == NIMG * 3 * 256 * 256) {
        const float* t = y; y = rgb; rgb = t;
    }

    dim3 grid(4, HH, NIMG);   // 1024 blocks, single wave at 7 blocks/SM
    crf_fused<<<grid, 128>>>(y, rgb, (float*)d_out);
}